// round 5
// baseline (speedup 1.0000x reference)
#include <cuda_runtime.h>
#include <math.h>

// Problem constants
#define B_  32
#define C_  512
#define T_  4000
#define NV_ 1000          // T/4 float4s
#define H4C 2048          // 4*C (stats width)
#define SP1 16            // gemm1 K-splits (K=2048, chunk 128)
#define SP2 8             // gemm2 K-splits (K=512,  chunk 64)
#define G1_BLOCKS 256     // 16 jtiles x 16 splits
#define G2_BLOCKS 256     // 32 jtiles x 8 kchunks

// ---------------- scratch (device globals; no allocation allowed) -----------
__device__ float g_statsT[H4C * B_];          // [2048][32]  feature-major, batch=lane
__device__ float g_hT[C_ * B_];               // [512][32]
__device__ float g_p1[SP1 * C_ * B_];         // gemm1 K-split partials
__device__ float g_p2[SP2 * 2 * C_ * B_];     // gemm2 K-split partials
__device__ int   g_jt_ctr[16];                // gemm1 jtile arrival counters (self-reset)
__device__ int   g_jt_flag[16];               // gemm1 jtile hT-ready flags   (self-reset)
__device__ int   g_done;                      // gemm2 completion counter     (self-reset)

// ---------------- kernel 1: fused add + 4-moment reduction ------------------
__global__ __launch_bounds__(256) void stats_kernel(
    const float* __restrict__ xa, const float* __restrict__ xb)
{
    int c = blockIdx.x;
    int b = blockIdx.y;
    size_t base = ((size_t)(b * C_ + c)) * T_;
    const float4* a4 = reinterpret_cast<const float4*>(xa + base);
    const float4* b4 = reinterpret_cast<const float4*>(xb + base);

    float s1 = 0.f, s2 = 0.f, s3 = 0.f, s4 = 0.f;
    for (int i = threadIdx.x; i < NV_; i += 256) {
        float4 av = a4[i];
        float4 bv = b4[i];
        float xv[4] = {av.x + bv.x, av.y + bv.y, av.z + bv.z, av.w + bv.w};
        #pragma unroll
        for (int q = 0; q < 4; q++) {
            float x = xv[q];
            float x2 = x * x;
            s1 += x;
            s2 = fmaf(x, x, s2);
            s3 = fmaf(x2, x, s3);
            s4 = fmaf(x2, x2, s4);
        }
    }
    #pragma unroll
    for (int off = 16; off > 0; off >>= 1) {
        s1 += __shfl_down_sync(0xffffffffu, s1, off);
        s2 += __shfl_down_sync(0xffffffffu, s2, off);
        s3 += __shfl_down_sync(0xffffffffu, s3, off);
        s4 += __shfl_down_sync(0xffffffffu, s4, off);
    }
    __shared__ float red[8][4];
    int w = threadIdx.x >> 5;
    if ((threadIdx.x & 31) == 0) {
        red[w][0] = s1; red[w][1] = s2; red[w][2] = s3; red[w][3] = s4;
    }
    __syncthreads();
    if (threadIdx.x == 0) {
        float t1 = 0.f, t2 = 0.f, t3 = 0.f, t4 = 0.f;
        #pragma unroll
        for (int i = 0; i < 8; i++) {
            t1 += red[i][0]; t2 += red[i][1]; t3 += red[i][2]; t4 += red[i][3];
        }
        const float Tf = (float)T_;
        float m  = t1 / Tf;
        float m2 = m * m;
        float sc2 = t2 - t1 * m;                       // sum centered^2
        float var = fmaxf(sc2 / (Tf - 1.0f), 0.f);     // unbiased
        float sd  = sqrtf(var);
        float d   = fmaxf(sd, 0.01f);                  // EPS clamp
        float sc3 = t3 - 3.f * m * t2 + 2.f * Tf * m * m2;
        float sc4 = t4 - 4.f * m * t3 + 6.f * m2 * t2 - 3.f * Tf * m2 * m2;
        float d3inv = 1.f / (Tf * d * d * d);
        float skew = sc3 * d3inv;
        float kurt = sc4 * d3inv / d;
        g_statsT[(c)            * B_ + b] = m;
        g_statsT[(C_ + c)       * B_ + b] = sd;
        g_statsT[(2 * C_ + c)   * B_ + b] = skew;
        g_statsT[(3 * C_ + c)   * B_ + b] = kurt;
    }
}

// ---------------- core GEMM tile: out[r][b] partial = A[r][i0:i0+KC].xT[..][b]
// sA/sX are caller-provided smem. Front-batched LDG.128 loads.
template<int KC>
__device__ __forceinline__ void gemm_core(
    const float* __restrict__ A, const float* __restrict__ xT,
    float* __restrict__ outP, int K, int rows, int j0, int i0, int sp,
    float* sA, float* sX, bool preloadedA)
{
    const int tid = threadIdx.x;
    constexpr int NF = KC / 32;   // float4s per thread per tile

    if (!preloadedA) {
        float4 va[NF];
        #pragma unroll
        for (int t = 0; t < NF; t++) {
            int f  = tid + t * 256;
            int jj = f / (KC / 4);
            int kq = f % (KC / 4);
            va[t] = *reinterpret_cast<const float4*>(A + (size_t)(j0 + jj) * K + i0 + 4 * kq);
        }
        #pragma unroll
        for (int t = 0; t < NF; t++)
            reinterpret_cast<float4*>(sA)[tid + t * 256] = va[t];
    }
    {
        float4 vx[NF];
        const float4* x4 = reinterpret_cast<const float4*>(xT + (size_t)i0 * B_);
        #pragma unroll
        for (int t = 0; t < NF; t++)
            vx[t] = x4[tid + t * 256];
        #pragma unroll
        for (int t = 0; t < NF; t++)
            reinterpret_cast<float4*>(sX)[tid + t * 256] = vx[t];
    }
    __syncthreads();

    const int b  = tid & 31;
    const int jb = (tid >> 5) * 4;
    float a0 = 0.f, a1 = 0.f, a2 = 0.f, a3 = 0.f;
    #pragma unroll 8
    for (int k4 = 0; k4 < KC / 4; k4++) {
        float4 r0 = reinterpret_cast<const float4*>(sA)[(jb + 0) * (KC / 4) + k4];
        float4 r1 = reinterpret_cast<const float4*>(sA)[(jb + 1) * (KC / 4) + k4];
        float4 r2 = reinterpret_cast<const float4*>(sA)[(jb + 2) * (KC / 4) + k4];
        float4 r3 = reinterpret_cast<const float4*>(sA)[(jb + 3) * (KC / 4) + k4];
        float s0 = sX[(4 * k4 + 0) * 32 + b];
        float s1 = sX[(4 * k4 + 1) * 32 + b];
        float s2 = sX[(4 * k4 + 2) * 32 + b];
        float s3 = sX[(4 * k4 + 3) * 32 + b];
        a0 = fmaf(r0.x, s0, a0); a0 = fmaf(r0.y, s1, a0); a0 = fmaf(r0.z, s2, a0); a0 = fmaf(r0.w, s3, a0);
        a1 = fmaf(r1.x, s0, a1); a1 = fmaf(r1.y, s1, a1); a1 = fmaf(r1.z, s2, a1); a1 = fmaf(r1.w, s3, a1);
        a2 = fmaf(r2.x, s0, a2); a2 = fmaf(r2.y, s1, a2); a2 = fmaf(r2.z, s2, a2); a2 = fmaf(r2.w, s3, a2);
        a3 = fmaf(r3.x, s0, a3); a3 = fmaf(r3.y, s1, a3); a3 = fmaf(r3.z, s2, a3); a3 = fmaf(r3.w, s3, a3);
    }
    size_t obase = (size_t)sp * rows * B_ + (size_t)(j0 + jb) * B_ + b;
    outP[obase + 0 * B_] = a0;
    outP[obase + 1 * B_] = a1;
    outP[obase + 2 * B_] = a2;
    outP[obase + 3 * B_] = a3;
}

// ---------------- fused mid-chain: gemm1 + reduce + gemm2 in one kernel -----
// bid < 256:  gemm1 split block (j = bid&15, sp = bid>>4). Last arriver per
//             jtile finalizes the 16-way reduction + bias -> g_hT, sets flag.
// bid >= 256: gemm2 block (j2, kc). Loads its W2 tile FIRST (overlaps gemm1),
//             then waits on the two hT jtile flags it needs, then computes.
// Last gemm2 block resets all counters/flags (stateless across replays).
__global__ __launch_bounds__(256) void midchain_kernel(
    const float* __restrict__ W1, const float* __restrict__ b1,
    const float* __restrict__ W2)
{
    __shared__ __align__(16) float sA[32 * 128];
    __shared__ __align__(16) float sX[128 * 32];
    const int bid = blockIdx.x;
    const int tid = threadIdx.x;

    if (bid < G1_BLOCKS) {
        int j  = bid & 15;
        int sp = bid >> 4;
        gemm_core<128>(W1, g_statsT, g_p1, H4C, C_, j * 32, sp * 128, sp, sA, sX, false);
        __threadfence();
        __shared__ int amLast;
        if (tid == 0) amLast = (atomicAdd(&g_jt_ctr[j], 1) == SP1 - 1);
        __syncthreads();
        if (amLast) {
            // finalize jtile j: 32 rows x 32 b = 1024 outputs, 4 per thread
            #pragma unroll
            for (int t = 0; t < 4; t++) {
                int il  = tid + t * 256;
                int row = il >> 5;
                int b   = il & 31;
                int r   = j * 32 + row;
                float acc = b1[r];
                #pragma unroll
                for (int s = 0; s < SP1; s++)
                    acc += g_p1[(size_t)s * (C_ * B_) + (size_t)r * B_ + b];
                g_hT[r * B_ + b] = acc;
            }
            __threadfence();
            __syncthreads();
            if (tid == 0) atomicExch(&g_jt_flag[j], 1);
        }
    } else {
        int bid2 = bid - G1_BLOCKS;
        int j2 = bid2 & 31;         // 32 jtiles over 2C rows
        int kc = bid2 >> 5;         // 8 k-chunks of 64
        int j0 = j2 * 32;
        int i0 = kc * 64;

        // Preload W2 tile into sA NOW (overlaps with gemm1 execution)
        {
            float4 va[2];
            #pragma unroll
            for (int t = 0; t < 2; t++) {
                int f  = tid + t * 256;
                int jj = f / 16;            // 64/4 = 16 f4 per row
                int kq = f % 16;
                va[t] = *reinterpret_cast<const float4*>(W2 + (size_t)(j0 + jj) * C_ + i0 + 4 * kq);
            }
            #pragma unroll
            for (int t = 0; t < 2; t++)
                reinterpret_cast<float4*>(sA)[tid + t * 256] = va[t];
        }

        // Wait for the two hT jtiles this k-chunk needs
        if (tid == 0) {
            while (atomicOr(&g_jt_flag[2 * kc], 0) == 0)     __nanosleep(64);
            while (atomicOr(&g_jt_flag[2 * kc + 1], 0) == 0) __nanosleep(64);
        }
        __syncthreads();
        __threadfence();

        gemm_core<64>(W2, g_hT, g_p2, C_, 2 * C_, j0, i0, kc, sA, sX, true);

        __threadfence();
        if (tid == 0) {
            int d = atomicAdd(&g_done, 1);
            if (d == G2_BLOCKS - 1) {        // last gemm2 block: reset state
                #pragma unroll
                for (int i = 0; i < 16; i++) { g_jt_ctr[i] = 0; g_jt_flag[i] = 0; }
                g_done = 0;
                __threadfence();
            }
        }
    }
}

// ---------------- kernel 3: gate reduce + softmax + weighted combine --------
// Blocks enumerate (c,b) in REVERSE order so the first reads hit the L2 tail
// left behind by stats_kernel.
__global__ __launch_bounds__(256) void apply_kernel(
    const float* __restrict__ xa, const float* __restrict__ xb,
    const float* __restrict__ b2, float* __restrict__ out)
{
    int lin = (B_ * C_ - 1) - (int)(blockIdx.y * C_ + blockIdx.x);
    int b = lin / C_;
    int c = lin - b * C_;

    float s0 = b2[c];
    float s1 = b2[C_ + c];
    #pragma unroll
    for (int sp = 0; sp < SP2; sp++) {
        s0 += g_p2[(size_t)sp * (2 * C_ * B_) + (size_t)c * B_ + b];
        s1 += g_p2[(size_t)sp * (2 * C_ * B_) + (size_t)(C_ + c) * B_ + b];
    }
    float mx = fmaxf(s0, s1);
    float e0 = __expf(s0 - mx);
    float e1 = __expf(s1 - mx);
    float inv = 1.f / (e0 + e1);
    float g0 = e0 * inv;
    float g1 = e1 * inv;

    size_t base = ((size_t)(b * C_ + c)) * T_;
    const float4* a4 = reinterpret_cast<const float4*>(xa + base);
    const float4* b4 = reinterpret_cast<const float4*>(xb + base);
    float4* o4 = reinterpret_cast<float4*>(out + base);
    for (int i = threadIdx.x; i < NV_; i += 256) {
        float4 av = a4[i];
        float4 bv = b4[i];
        float4 r;
        r.x = fmaf(av.x, g0, bv.x * g1);
        r.y = fmaf(av.y, g0, bv.y * g1);
        r.z = fmaf(av.z, g0, bv.z * g1);
        r.w = fmaf(av.w, g0, bv.w * g1);
        o4[i] = r;
    }
}

// ---------------- launcher --------------------------------------------------
extern "C" void kernel_launch(void* const* d_in, const int* in_sizes, int n_in,
                              void* d_out, int out_size)
{
    const float* xa = (const float*)d_in[0];
    const float* xb = (const float*)d_in[1];
    const float* W1 = (const float*)d_in[2];
    const float* b1 = (const float*)d_in[3];
    const float* W2 = (const float*)d_in[4];
    const float* b2 = (const float*)d_in[5];
    float* out = (float*)d_out;

    stats_kernel<<<dim3(C_, B_), 256>>>(xa, xb);
    midchain_kernel<<<G1_BLOCKS + G2_BLOCKS, 256>>>(W1, b1, W2);
    apply_kernel<<<dim3(C_, B_), 256>>>(xa, xb, b2, out);
}

// round 6
// speedup vs baseline: 1.0096x; 1.0096x over previous
#include <cuda_runtime.h>
#include <math.h>

// Problem constants
#define B_  32
#define C_  512
#define T_  4000
#define NV_ 1000          // T/4 float4s
#define H4C 2048          // 4*C (stats width)
#define SP1 16            // gemm1 K-splits (K=2048, chunk 128)
#define SP2 8             // gemm2 K-splits (K=512,  chunk 64)

// ---------------- scratch (device globals; no allocation allowed) -----------
__device__ float g_statsT[H4C * B_];          // [2048][32]  feature-major, batch=lane
__device__ float g_hT[C_ * B_];               // [512][32]
__device__ float g_p1[SP1 * C_ * B_];         // gemm1 K-split partials
__device__ float g_p2[SP2 * 2 * C_ * B_];     // gemm2 K-split partials

// ---------------- kernel 1: fused add + 4-moment reduction ------------------
__global__ __launch_bounds__(256) void stats_kernel(
    const float* __restrict__ xa, const float* __restrict__ xb)
{
    int c = blockIdx.x;
    int b = blockIdx.y;
    size_t base = ((size_t)(b * C_ + c)) * T_;
    const float4* a4 = reinterpret_cast<const float4*>(xa + base);
    const float4* b4 = reinterpret_cast<const float4*>(xb + base);

    float s1 = 0.f, s2 = 0.f, s3 = 0.f, s4 = 0.f;
    for (int i = threadIdx.x; i < NV_; i += 256) {
        float4 av = a4[i];
        float4 bv = b4[i];
        float xv[4] = {av.x + bv.x, av.y + bv.y, av.z + bv.z, av.w + bv.w};
        #pragma unroll
        for (int q = 0; q < 4; q++) {
            float x = xv[q];
            float x2 = x * x;
            s1 += x;
            s2 = fmaf(x, x, s2);
            s3 = fmaf(x2, x, s3);
            s4 = fmaf(x2, x2, s4);
        }
    }
    #pragma unroll
    for (int off = 16; off > 0; off >>= 1) {
        s1 += __shfl_down_sync(0xffffffffu, s1, off);
        s2 += __shfl_down_sync(0xffffffffu, s2, off);
        s3 += __shfl_down_sync(0xffffffffu, s3, off);
        s4 += __shfl_down_sync(0xffffffffu, s4, off);
    }
    __shared__ float red[8][4];
    int w = threadIdx.x >> 5;
    if ((threadIdx.x & 31) == 0) {
        red[w][0] = s1; red[w][1] = s2; red[w][2] = s3; red[w][3] = s4;
    }
    __syncthreads();
    if (threadIdx.x == 0) {
        float t1 = 0.f, t2 = 0.f, t3 = 0.f, t4 = 0.f;
        #pragma unroll
        for (int i = 0; i < 8; i++) {
            t1 += red[i][0]; t2 += red[i][1]; t3 += red[i][2]; t4 += red[i][3];
        }
        const float Tf = (float)T_;
        float m  = t1 / Tf;
        float m2 = m * m;
        float sc2 = t2 - t1 * m;                       // sum centered^2
        float var = fmaxf(sc2 / (Tf - 1.0f), 0.f);     // unbiased
        float sd  = sqrtf(var);
        float d   = fmaxf(sd, 0.01f);                  // EPS clamp
        float sc3 = t3 - 3.f * m * t2 + 2.f * Tf * m * m2;
        float sc4 = t4 - 4.f * m * t3 + 6.f * m2 * t2 - 3.f * Tf * m2 * m2;
        float d3inv = 1.f / (Tf * d * d * d);
        float skew = sc3 * d3inv;
        float kurt = sc4 * d3inv / d;
        g_statsT[(c)            * B_ + b] = m;
        g_statsT[(C_ + c)       * B_ + b] = sd;
        g_statsT[(2 * C_ + c)   * B_ + b] = skew;
        g_statsT[(3 * C_ + c)   * B_ + b] = kurt;
    }
}

// ---------------- mini-GEMM: out[r][b] partials = A[r][:K] . xT[:K][b]
// Block: 32 output rows x 32 batch, K-chunk KC per blockIdx.y.
// Front-batched LDG.128 tile loads, conflict-free STS.128, inner loop of
// broadcast LDS.128 + lane-distinct LDS.32.
template<int KC>
__device__ __forceinline__ void gemm_tile(
    const float* __restrict__ A, const float* __restrict__ xT,
    float* __restrict__ outP, int K, int rows)
{
    __shared__ __align__(16) float sA[32 * KC];   // [jj][k] row-major
    __shared__ __align__(16) float sX[KC * 32];   // [k][b]
    const int j0 = blockIdx.x * 32;
    const int i0 = blockIdx.y * KC;
    const int tid = threadIdx.x;

    constexpr int NF = KC / 32;   // float4s per thread for each tile
    float4 va[NF], vx[NF];
    #pragma unroll
    for (int t = 0; t < NF; t++) {
        int f  = tid + t * 256;            // f4 index in [0, 8*KC)
        int jj = f / (KC / 4);
        int kq = f % (KC / 4);
        va[t] = *reinterpret_cast<const float4*>(A + (size_t)(j0 + jj) * K + i0 + 4 * kq);
    }
    {
        const float4* x4 = reinterpret_cast<const float4*>(xT + (size_t)i0 * B_);
        #pragma unroll
        for (int t = 0; t < NF; t++)
            vx[t] = x4[tid + t * 256];
    }
    #pragma unroll
    for (int t = 0; t < NF; t++)
        reinterpret_cast<float4*>(sA)[tid + t * 256] = va[t];
    #pragma unroll
    for (int t = 0; t < NF; t++)
        reinterpret_cast<float4*>(sX)[tid + t * 256] = vx[t];
    __syncthreads();

    const int b  = tid & 31;
    const int jb = (tid >> 5) * 4;     // 8 warps * 4 rows = 32 rows
    float a0 = 0.f, a1 = 0.f, a2 = 0.f, a3 = 0.f;
    #pragma unroll 8
    for (int k4 = 0; k4 < KC / 4; k4++) {
        float4 r0 = reinterpret_cast<const float4*>(sA)[(jb + 0) * (KC / 4) + k4];
        float4 r1 = reinterpret_cast<const float4*>(sA)[(jb + 1) * (KC / 4) + k4];
        float4 r2 = reinterpret_cast<const float4*>(sA)[(jb + 2) * (KC / 4) + k4];
        float4 r3 = reinterpret_cast<const float4*>(sA)[(jb + 3) * (KC / 4) + k4];
        float s0 = sX[(4 * k4 + 0) * 32 + b];
        float s1 = sX[(4 * k4 + 1) * 32 + b];
        float s2 = sX[(4 * k4 + 2) * 32 + b];
        float s3 = sX[(4 * k4 + 3) * 32 + b];
        a0 = fmaf(r0.x, s0, a0); a0 = fmaf(r0.y, s1, a0); a0 = fmaf(r0.z, s2, a0); a0 = fmaf(r0.w, s3, a0);
        a1 = fmaf(r1.x, s0, a1); a1 = fmaf(r1.y, s1, a1); a1 = fmaf(r1.z, s2, a1); a1 = fmaf(r1.w, s3, a1);
        a2 = fmaf(r2.x, s0, a2); a2 = fmaf(r2.y, s1, a2); a2 = fmaf(r2.z, s2, a2); a2 = fmaf(r2.w, s3, a2);
        a3 = fmaf(r3.x, s0, a3); a3 = fmaf(r3.y, s1, a3); a3 = fmaf(r3.z, s2, a3); a3 = fmaf(r3.w, s3, a3);
    }
    size_t obase = (size_t)blockIdx.y * rows * B_ + (size_t)(j0 + jb) * B_ + b;
    outP[obase + 0 * B_] = a0;
    outP[obase + 1 * B_] = a1;
    outP[obase + 2 * B_] = a2;
    outP[obase + 3 * B_] = a3;
}

__global__ __launch_bounds__(256) void gemm1_kernel(const float* __restrict__ W1)
{
    gemm_tile<128>(W1, g_statsT, g_p1, H4C, C_);
}

__global__ __launch_bounds__(256) void reduce1_kernel(const float* __restrict__ b1)
{
    int idx4 = blockIdx.x * 256 + threadIdx.x;    // over C_*B_/4 = 4096 float4s
    if (idx4 >= C_ * B_ / 4) return;
    float bv = b1[idx4 >> 3];                     // 8 f4s (32 scalars) per channel
    float4 acc = make_float4(bv, bv, bv, bv);
    #pragma unroll
    for (int sp = 0; sp < SP1; sp++) {
        float4 p = reinterpret_cast<const float4*>(g_p1)[sp * (C_ * B_ / 4) + idx4];
        acc.x += p.x; acc.y += p.y; acc.z += p.z; acc.w += p.w;
    }
    reinterpret_cast<float4*>(g_hT)[idx4] = acc;
}

__global__ __launch_bounds__(256) void gemm2_kernel(const float* __restrict__ W2)
{
    gemm_tile<64>(W2, g_hT, g_p2, C_, 2 * C_);
}

// ---------------- kernel 5: gate reduce + softmax + weighted combine --------
// Reverse (c,b) order so first reads hit the stats-kernel L2 tail; output
// stores use evict-first streaming (__stcs) so the 262MB of writes do NOT
// evict the resident xa/xb read data from L2.
__global__ __launch_bounds__(256) void apply_kernel(
    const float* __restrict__ xa, const float* __restrict__ xb,
    const float* __restrict__ b2, float* __restrict__ out)
{
    int lin = (B_ * C_ - 1) - (int)(blockIdx.y * C_ + blockIdx.x);
    int b = lin / C_;
    int c = lin - b * C_;

    // finish gate GEMM reduction (fixed order) + bias, redundantly per thread
    float s0 = b2[c];
    float s1 = b2[C_ + c];
    #pragma unroll
    for (int sp = 0; sp < SP2; sp++) {
        s0 += g_p2[(size_t)sp * (2 * C_ * B_) + (size_t)c * B_ + b];
        s1 += g_p2[(size_t)sp * (2 * C_ * B_) + (size_t)(C_ + c) * B_ + b];
    }
    float mx = fmaxf(s0, s1);
    float e0 = __expf(s0 - mx);
    float e1 = __expf(s1 - mx);
    float inv = 1.f / (e0 + e1);
    float g0 = e0 * inv;
    float g1 = e1 * inv;

    size_t base = ((size_t)(b * C_ + c)) * T_;
    const float4* a4 = reinterpret_cast<const float4*>(xa + base);
    const float4* b4 = reinterpret_cast<const float4*>(xb + base);
    float4* o4 = reinterpret_cast<float4*>(out + base);
    for (int i = threadIdx.x; i < NV_; i += 256) {
        float4 av = a4[i];
        float4 bv = b4[i];
        float4 r;
        r.x = fmaf(av.x, g0, bv.x * g1);
        r.y = fmaf(av.y, g0, bv.y * g1);
        r.z = fmaf(av.z, g0, bv.z * g1);
        r.w = fmaf(av.w, g0, bv.w * g1);
        __stcs(&o4[i], r);       // streaming store: evict-first, keep reads hot
    }
}

// ---------------- launcher --------------------------------------------------
extern "C" void kernel_launch(void* const* d_in, const int* in_sizes, int n_in,
                              void* d_out, int out_size)
{
    const float* xa = (const float*)d_in[0];
    const float* xb = (const float*)d_in[1];
    const float* W1 = (const float*)d_in[2];
    const float* b1 = (const float*)d_in[3];
    const float* W2 = (const float*)d_in[4];
    const float* b2 = (const float*)d_in[5];
    float* out = (float*)d_out;

    stats_kernel<<<dim3(C_, B_), 256>>>(xa, xb);
    gemm1_kernel<<<dim3(C_ / 32, SP1), 256>>>(W1);                // 16 x 16
    reduce1_kernel<<<C_ * B_ / 4 / 256, 256>>>(b1);               // 16 blocks
    gemm2_kernel<<<dim3(2 * C_ / 32, SP2), 256>>>(W2);            // 32 x 8
    apply_kernel<<<dim3(C_, B_), 256>>>(xa, xb, b2, out);
}

// round 7
// speedup vs baseline: 1.0276x; 1.0178x over previous
#include <cuda_runtime.h>
#include <math.h>

// Problem constants
#define B_  32
#define C_  512
#define T_  4000
#define NV_ 1000          // T/4 float4s
#define H4C 2048          // 4*C (stats width)
#define SP1 16            // gemm1 K-splits (K=2048, chunk 128)
#define SP2 8             // gemm2 K-splits (K=512,  chunk 64)

// ---------------- scratch (device globals; no allocation allowed) -----------
__device__ float g_statsT[H4C * B_];          // [2048][32]  feature-major, batch=lane
__device__ float g_hT[C_ * B_];               // [512][32]
__device__ float g_p1[SP1 * C_ * B_];         // gemm1 K-split partials
__device__ float g_p2[SP2 * 2 * C_ * B_];     // gemm2 K-split partials

// ---------------- kernel 1: fused add + 4-moment reduction ------------------
__global__ __launch_bounds__(256) void stats_kernel(
    const float* __restrict__ xa, const float* __restrict__ xb)
{
    int c = blockIdx.x;
    int b = blockIdx.y;
    size_t base = ((size_t)(b * C_ + c)) * T_;
    const float4* a4 = reinterpret_cast<const float4*>(xa + base);
    const float4* b4 = reinterpret_cast<const float4*>(xb + base);

    float s1 = 0.f, s2 = 0.f, s3 = 0.f, s4 = 0.f;
    for (int i = threadIdx.x; i < NV_; i += 256) {
        float4 av = a4[i];
        float4 bv = b4[i];
        float xv[4] = {av.x + bv.x, av.y + bv.y, av.z + bv.z, av.w + bv.w};
        #pragma unroll
        for (int q = 0; q < 4; q++) {
            float x = xv[q];
            float x2 = x * x;
            s1 += x;
            s2 = fmaf(x, x, s2);
            s3 = fmaf(x2, x, s3);
            s4 = fmaf(x2, x2, s4);
        }
    }
    #pragma unroll
    for (int off = 16; off > 0; off >>= 1) {
        s1 += __shfl_down_sync(0xffffffffu, s1, off);
        s2 += __shfl_down_sync(0xffffffffu, s2, off);
        s3 += __shfl_down_sync(0xffffffffu, s3, off);
        s4 += __shfl_down_sync(0xffffffffu, s4, off);
    }
    __shared__ float red[8][4];
    int w = threadIdx.x >> 5;
    if ((threadIdx.x & 31) == 0) {
        red[w][0] = s1; red[w][1] = s2; red[w][2] = s3; red[w][3] = s4;
    }
    __syncthreads();
    if (threadIdx.x == 0) {
        float t1 = 0.f, t2 = 0.f, t3 = 0.f, t4 = 0.f;
        #pragma unroll
        for (int i = 0; i < 8; i++) {
            t1 += red[i][0]; t2 += red[i][1]; t3 += red[i][2]; t4 += red[i][3];
        }
        const float Tf = (float)T_;
        float m  = t1 / Tf;
        float m2 = m * m;
        float sc2 = t2 - t1 * m;                       // sum centered^2
        float var = fmaxf(sc2 / (Tf - 1.0f), 0.f);     // unbiased
        float sd  = sqrtf(var);
        float d   = fmaxf(sd, 0.01f);                  // EPS clamp
        float sc3 = t3 - 3.f * m * t2 + 2.f * Tf * m * m2;
        float sc4 = t4 - 4.f * m * t3 + 6.f * m2 * t2 - 3.f * Tf * m2 * m2;
        float d3inv = 1.f / (Tf * d * d * d);
        float skew = sc3 * d3inv;
        float kurt = sc4 * d3inv / d;
        g_statsT[(c)            * B_ + b] = m;
        g_statsT[(C_ + c)       * B_ + b] = sd;
        g_statsT[(2 * C_ + c)   * B_ + b] = skew;
        g_statsT[(3 * C_ + c)   * B_ + b] = kurt;
    }
}

// ---------------- mini-GEMM: out[r][b] partials = A[r][:K] . xT[:K][b]
// Weight tile (A) is loaded into registers BEFORE cudaGridDependencySynchronize
// so the cold DRAM fetch overlaps the predecessor kernel (PDL). xT (produced
// by the predecessor chain) is only read after the sync.
template<int KC>
__device__ __forceinline__ void gemm_tile_pdl(
    const float* __restrict__ A, const float* __restrict__ xT,
    float* __restrict__ outP, int K, int rows)
{
    __shared__ __align__(16) float sA[32 * KC];   // [jj][k] row-major
    __shared__ __align__(16) float sX[KC * 32];   // [k][b]
    const int j0 = blockIdx.x * 32;
    const int i0 = blockIdx.y * KC;
    const int tid = threadIdx.x;

    constexpr int NF = KC / 32;   // float4s per thread for each tile
    float4 va[NF];
    #pragma unroll
    for (int t = 0; t < NF; t++) {
        int f  = tid + t * 256;            // f4 index in [0, 8*KC)
        int jj = f / (KC / 4);
        int kq = f % (KC / 4);
        va[t] = *reinterpret_cast<const float4*>(A + (size_t)(j0 + jj) * K + i0 + 4 * kq);
    }

    cudaGridDependencySynchronize();       // predecessor results now visible

    {
        float4 vx[NF];
        const float4* x4 = reinterpret_cast<const float4*>(xT + (size_t)i0 * B_);
        #pragma unroll
        for (int t = 0; t < NF; t++)
            vx[t] = x4[tid + t * 256];
        #pragma unroll
        for (int t = 0; t < NF; t++)
            reinterpret_cast<float4*>(sX)[tid + t * 256] = vx[t];
    }
    #pragma unroll
    for (int t = 0; t < NF; t++)
        reinterpret_cast<float4*>(sA)[tid + t * 256] = va[t];
    __syncthreads();

    const int b  = tid & 31;
    const int jb = (tid >> 5) * 4;     // 8 warps * 4 rows = 32 rows
    float a0 = 0.f, a1 = 0.f, a2 = 0.f, a3 = 0.f;
    #pragma unroll 8
    for (int k4 = 0; k4 < KC / 4; k4++) {
        float4 r0 = reinterpret_cast<const float4*>(sA)[(jb + 0) * (KC / 4) + k4];
        float4 r1 = reinterpret_cast<const float4*>(sA)[(jb + 1) * (KC / 4) + k4];
        float4 r2 = reinterpret_cast<const float4*>(sA)[(jb + 2) * (KC / 4) + k4];
        float4 r3 = reinterpret_cast<const float4*>(sA)[(jb + 3) * (KC / 4) + k4];
        float s0 = sX[(4 * k4 + 0) * 32 + b];
        float s1 = sX[(4 * k4 + 1) * 32 + b];
        float s2 = sX[(4 * k4 + 2) * 32 + b];
        float s3 = sX[(4 * k4 + 3) * 32 + b];
        a0 = fmaf(r0.x, s0, a0); a0 = fmaf(r0.y, s1, a0); a0 = fmaf(r0.z, s2, a0); a0 = fmaf(r0.w, s3, a0);
        a1 = fmaf(r1.x, s0, a1); a1 = fmaf(r1.y, s1, a1); a1 = fmaf(r1.z, s2, a1); a1 = fmaf(r1.w, s3, a1);
        a2 = fmaf(r2.x, s0, a2); a2 = fmaf(r2.y, s1, a2); a2 = fmaf(r2.z, s2, a2); a2 = fmaf(r2.w, s3, a2);
        a3 = fmaf(r3.x, s0, a3); a3 = fmaf(r3.y, s1, a3); a3 = fmaf(r3.z, s2, a3); a3 = fmaf(r3.w, s3, a3);
    }
    size_t obase = (size_t)blockIdx.y * rows * B_ + (size_t)(j0 + jb) * B_ + b;
    outP[obase + 0 * B_] = a0;
    outP[obase + 1 * B_] = a1;
    outP[obase + 2 * B_] = a2;
    outP[obase + 3 * B_] = a3;
}

__global__ __launch_bounds__(256) void gemm1_kernel(const float* __restrict__ W1)
{
    gemm_tile_pdl<128>(W1, g_statsT, g_p1, H4C, C_);
}

__global__ __launch_bounds__(256) void reduce1_kernel(const float* __restrict__ b1)
{
    int idx4 = blockIdx.x * 256 + threadIdx.x;    // over C_*B_/4 = 4096 float4s
    float bv = (idx4 < C_ * B_ / 4) ? b1[idx4 >> 3] : 0.f;   // input: safe pre-sync
    cudaGridDependencySynchronize();
    if (idx4 >= C_ * B_ / 4) return;
    float4 acc = make_float4(bv, bv, bv, bv);
    #pragma unroll
    for (int sp = 0; sp < SP1; sp++) {
        float4 p = reinterpret_cast<const float4*>(g_p1)[sp * (C_ * B_ / 4) + idx4];
        acc.x += p.x; acc.y += p.y; acc.z += p.z; acc.w += p.w;
    }
    reinterpret_cast<float4*>(g_hT)[idx4] = acc;
}

__global__ __launch_bounds__(256) void gemm2_kernel(const float* __restrict__ W2)
{
    gemm_tile_pdl<64>(W2, g_hT, g_p2, C_, 2 * C_);
}

// ---------------- kernel 5: gate reduce + softmax + weighted combine --------
__global__ __launch_bounds__(256) void apply_kernel(
    const float* __restrict__ xa, const float* __restrict__ xb,
    const float* __restrict__ b2, float* __restrict__ out)
{
    int lin = (B_ * C_ - 1) - (int)(blockIdx.y * C_ + blockIdx.x);
    int b = lin / C_;
    int c = lin - b * C_;

    // inputs (independent of predecessors): read before sync
    float s0 = b2[c];
    float s1 = b2[C_ + c];

    cudaGridDependencySynchronize();       // g_p2 now visible

    #pragma unroll
    for (int sp = 0; sp < SP2; sp++) {
        s0 += g_p2[(size_t)sp * (2 * C_ * B_) + (size_t)c * B_ + b];
        s1 += g_p2[(size_t)sp * (2 * C_ * B_) + (size_t)(C_ + c) * B_ + b];
    }
    float mx = fmaxf(s0, s1);
    float e0 = __expf(s0 - mx);
    float e1 = __expf(s1 - mx);
    float inv = 1.f / (e0 + e1);
    float g0 = e0 * inv;
    float g1 = e1 * inv;

    size_t base = ((size_t)(b * C_ + c)) * T_;
    const float4* a4 = reinterpret_cast<const float4*>(xa + base);
    const float4* b4 = reinterpret_cast<const float4*>(xb + base);
    float4* o4 = reinterpret_cast<float4*>(out + base);
    for (int i = threadIdx.x; i < NV_; i += 256) {
        float4 av = a4[i];
        float4 bv = b4[i];
        float4 r;
        r.x = fmaf(av.x, g0, bv.x * g1);
        r.y = fmaf(av.y, g0, bv.y * g1);
        r.z = fmaf(av.z, g0, bv.z * g1);
        r.w = fmaf(av.w, g0, bv.w * g1);
        __stcs(&o4[i], r);       // streaming store: evict-first, keep reads hot
    }
}

// ---------------- launcher --------------------------------------------------
static inline void launch_pdl(const void* fn, dim3 grid, dim3 block,
                              void** args)
{
    cudaLaunchConfig_t cfg = {};
    cfg.gridDim  = grid;
    cfg.blockDim = block;
    cfg.dynamicSmemBytes = 0;
    cfg.stream = 0;
    cudaLaunchAttribute attr[1];
    attr[0].id = cudaLaunchAttributeProgrammaticStreamSerialization;
    attr[0].val.programmaticStreamSerializationAllowed = 1;
    cfg.attrs = attr;
    cfg.numAttrs = 1;
    cudaLaunchKernelExC(&cfg, fn, args);
}

extern "C" void kernel_launch(void* const* d_in, const int* in_sizes, int n_in,
                              void* d_out, int out_size)
{
    const float* xa = (const float*)d_in[0];
    const float* xb = (const float*)d_in[1];
    const float* W1 = (const float*)d_in[2];
    const float* b1 = (const float*)d_in[3];
    const float* W2 = (const float*)d_in[4];
    const float* b2 = (const float*)d_in[5];
    float* out = (float*)d_out;

    stats_kernel<<<dim3(C_, B_), 256>>>(xa, xb);

    {   // gemm1: PDL secondary of stats (W1 preload overlaps stats tail)
        void* args[] = { (void*)&W1 };
        launch_pdl((const void*)gemm1_kernel, dim3(C_ / 32, SP1), dim3(256), args);
    }
    {   // reduce1: PDL secondary of gemm1
        void* args[] = { (void*)&b1 };
        launch_pdl((const void*)reduce1_kernel, dim3(C_ * B_ / 4 / 256), dim3(256), args);
    }
    {   // gemm2: PDL secondary of reduce1 (W2 preload overlaps)
        void* args[] = { (void*)&W2 };
        launch_pdl((const void*)gemm2_kernel, dim3(2 * C_ / 32, SP2), dim3(256), args);
    }
    {   // apply: PDL secondary of gemm2 (ramp hidden)
        void* args[] = { (void*)&xa, (void*)&xb, (void*)&b2, (void*)&out };
        launch_pdl((const void*)apply_kernel, dim3(C_, B_), dim3(256), args);
    }
}